// round 17
// baseline (speedup 1.0000x reference)
#include <cuda_runtime.h>
#include <cuda_bf16.h>
#include <cstdint>
#include <cstddef>

#define Mdim 128
#define Ndim 64
#define Edim 32
#define Sdim 512
#define Bdim 8192

typedef unsigned long long ull;

// ---------------- scratch (no allocation allowed) ----------------
__device__ float g_zc[Bdim * Ndim];                    // z_cur transposed: [b*64 + i]
__device__ float g_w [Bdim * Edim];                    // expert weights:   [b*32 + e]
__device__ __nv_bfloat16 g_wx_hi[Edim * Mdim * Mdim];  // Wx hi bf16 [e][m][k]
__device__ __nv_bfloat16 g_wx_lo[Edim * Mdim * Mdim];  // Wx lo bf16

// ---------------- Kernel C0: Wx -> bf16 hi/lo ----------------
__global__ void k_conv(const float* __restrict__ Wx)
{
    int idx = blockIdx.x * 256 + threadIdx.x;
    float v = Wx[idx];
    __nv_bfloat16 h = __float2bfloat16(v);
    g_wx_hi[idx] = h;
    g_wx_lo[idx] = __float2bfloat16(v - __bfloat162float(h));
}

// ---------------- Kernel 1: z_cur = D @ z + sigma_g * noise (transposed out) ----------------
__global__ void k_zc(const float* __restrict__ z, const float* __restrict__ noise,
                     const float* __restrict__ Dm, const float* __restrict__ sigma_g)
{
    int b = blockIdx.x * blockDim.x + threadIdx.x;
    int i = blockIdx.y;
    float acc = sigma_g[i] * noise[(size_t)i * Bdim + b];
    const float* drow = Dm + i * Mdim;
    #pragma unroll 8
    for (int m = 0; m < Mdim; ++m)
        acc = fmaf(drow[m], z[(size_t)m * Bdim + b], acc);
    g_zc[(size_t)b * Ndim + i] = acc;
}

// ---------------- Kernel 2: streaming online-softmax attention + conv-emb + MLP + expert softmax ----------------
#define K2_WARPS 8
#define CHUNK 8

struct OnlineState {
    float mrun, denom, pprev;
    float c0x, c0y, c1x, c1y;
};

__device__ __forceinline__ void row_proc(const float2 v, float zcx, float zcy,
                                         float invT1, OnlineState& st)
{
    float dd = fabsf(v.x - zcx) + fabsf(v.y - zcy);
    dd += __shfl_xor_sync(0xffffffffu, dd, 16);
    dd += __shfl_xor_sync(0xffffffffu, dd, 8);
    dd += __shfl_xor_sync(0xffffffffu, dd, 4);
    dd += __shfl_xor_sync(0xffffffffu, dd, 2);
    dd += __shfl_xor_sync(0xffffffffu, dd, 1);
    float logit = -dd * invT1;
    if (logit > st.mrun) {
        float s = __expf(st.mrun - logit);
        st.denom *= s; st.c0x *= s; st.c0y *= s; st.c1x *= s; st.c1y *= s; st.pprev *= s;
        st.mrun = logit;
    }
    float pw = __expf(logit - st.mrun);
    st.denom += pw;
    st.c0x = fmaf(pw, v.x, st.c0x);       st.c0y = fmaf(pw, v.y, st.c0y);
    st.c1x = fmaf(st.pprev, v.x, st.c1x); st.c1y = fmaf(st.pprev, v.y, st.c1y);
    st.pprev = pw;
}

__device__ __forceinline__ void load_chunk(float2* buf, const float2* p, size_t TSTEP, int cidx)
{
    const float2* q = p + (size_t)cidx * (size_t)CHUNK * TSTEP;
    #pragma unroll
    for (int r = 0; r < CHUNK; ++r) buf[r] = __ldcs(q + (size_t)r * TSTEP);
}

__device__ __forceinline__ void proc_chunk(const float2* buf, float zcx, float zcy,
                                           float invT1, OnlineState& st)
{
    #pragma unroll
    for (int r = 0; r < CHUNK; ++r) row_proc(buf[r], zcx, zcy, invT1, st);
}

__global__ __launch_bounds__(256, 4)
void k_attn(const float* __restrict__ ctx, const float* __restrict__ z,
            const float* __restrict__ conv_w, const float* __restrict__ conv_b,
            const float* __restrict__ temp1,
            const float* __restrict__ W1, const float* __restrict__ b1,
            const float* __restrict__ W2, const float* __restrict__ b2,
            const float* __restrict__ temp2)
{
    __shared__ float W1s[192 * 32];
    __shared__ float W2s[32 * 32];
    __shared__ float scomb[K2_WARPS][194];

    int tid = threadIdx.x;
    for (int t = tid; t < 192 * 32; t += 256) {
        int e = t / 192, j = t % 192;
        W1s[j * 32 + e] = W1[t];
    }
    for (int t = tid; t < 32 * 32; t += 256) {
        int e = t / 32, j = t % 32;
        W2s[j * 32 + e] = W2[t];
    }
    __syncthreads();

    int warp = tid >> 5, lane = tid & 31;
    int b = blockIdx.x * K2_WARPS + warp;

    float invT1 = 1.0f / fabsf(temp1[0]);
    float invT2 = 1.0f / fabsf(temp2[0]);

    float zcx = g_zc[(size_t)b * Ndim + 2 * lane];
    float zcy = g_zc[(size_t)b * Ndim + 2 * lane + 1];

    const float2* p = reinterpret_cast<const float2*>(ctx) + (size_t)b * (Ndim / 2) + lane;
    const size_t TSTEP = (size_t)Bdim * (Ndim / 2);

    OnlineState st;
    st.mrun = -1e30f; st.denom = 0.f; st.pprev = 0.f;
    st.c0x = 0.f; st.c0y = 0.f; st.c1x = 0.f; st.c1y = 0.f;
    float2 buf0[CHUNK], buf1[CHUNK];

    load_chunk(buf0, p, TSTEP, 0);
    for (int cc = 0; cc < 62; cc += 2) {
        load_chunk(buf1, p, TSTEP, cc + 1);
        proc_chunk(buf0, zcx, zcy, invT1, st);
        load_chunk(buf0, p, TSTEP, cc + 2);
        proc_chunk(buf1, zcx, zcy, invT1, st);
    }
    load_chunk(buf1, p, TSTEP, 63);
    proc_chunk(buf0, zcx, zcy, invT1, st);
    #pragma unroll
    for (int r = 0; r < CHUNK - 1; ++r) row_proc(buf1[r], zcx, zcy, invT1, st);
    {
        float2 v = buf1[CHUNK - 1];
        st.c1x = fmaf(st.pprev, v.x, st.c1x);
        st.c1y = fmaf(st.pprev, v.y, st.c1y);
    }

    float rinv = 1.0f / st.denom;
    float* sc = scomb[warp];
    sc[2 * lane]      = st.c0x * rinv;  sc[2 * lane + 1]      = st.c0y * rinv;
    sc[64 + 2 * lane] = st.c1x * rinv;  sc[64 + 2 * lane + 1] = st.c1y * rinv;
    __syncwarp();

    int o0 = 2 * lane, o1 = 2 * lane + 1;
    float e0 = conv_b[o0], e1 = conv_b[o1];
    const float* cwA = conv_w + (size_t)o0 * 128;
    const float* cwB = conv_w + (size_t)o1 * 128;
    #pragma unroll 8
    for (int i = 0; i < 64; ++i) {
        float a = sc[i], c = sc[64 + i];
        e0 = fmaf(__ldg(cwA + 2 * i), a, e0);
        e0 = fmaf(__ldg(cwA + 2 * i + 1), c, e0);
        e1 = fmaf(__ldg(cwB + 2 * i), a, e1);
        e1 = fmaf(__ldg(cwB + 2 * i + 1), c, e1);
    }
    __syncwarp();
    sc[o0] = e0; sc[o1] = e1;
    #pragma unroll
    for (int k = 0; k < 4; ++k) {
        int j = lane * 4 + k;
        sc[64 + j] = __ldg(z + (size_t)j * Bdim + b);
    }
    __syncwarp();

    float hs = b1[lane];
    #pragma unroll 8
    for (int j = 0; j < 192; ++j)
        hs = fmaf(W1s[j * 32 + lane], sc[j], hs);
    hs = fmaxf(hs, 0.f);

    float o2 = b2[lane];
    #pragma unroll
    for (int j = 0; j < 32; ++j)
        o2 = fmaf(W2s[j * 32 + lane], __shfl_sync(0xffffffffu, hs, j), o2);

    float lg = -o2 * invT2;
    float mx = lg;
    mx = fmaxf(mx, __shfl_xor_sync(0xffffffffu, mx, 16));
    mx = fmaxf(mx, __shfl_xor_sync(0xffffffffu, mx, 8));
    mx = fmaxf(mx, __shfl_xor_sync(0xffffffffu, mx, 4));
    mx = fmaxf(mx, __shfl_xor_sync(0xffffffffu, mx, 2));
    mx = fmaxf(mx, __shfl_xor_sync(0xffffffffu, mx, 1));
    float pw2 = __expf(lg - mx);
    float sm2 = pw2;
    sm2 += __shfl_xor_sync(0xffffffffu, sm2, 16);
    sm2 += __shfl_xor_sync(0xffffffffu, sm2, 8);
    sm2 += __shfl_xor_sync(0xffffffffu, sm2, 4);
    sm2 += __shfl_xor_sync(0xffffffffu, sm2, 2);
    sm2 += __shfl_xor_sync(0xffffffffu, sm2, 1);
    g_w[(size_t)b * 32 + lane] = pw2 / sm2;
}

// ---------------- Kernel 3: mma.sync bf16 hi/lo, double-buffered pipeline ----------------
// D1[m,b] = sum_{e,k} Wx[e,m,k]*(w[e,b]*zcat[k,b]) + sum_e h[e,m]w[e,b]
// D2[m,b] = sum_e A[e,m]w[e,b];   out = D1 + z .* D2
#define NB 32
#define NTILES_N (NB / 8)
#define APAD 40

// dynamic smem layout (bytes)
#define SM_AHI 0                     // [2][128][APAD] bf16 = 20480
#define SM_ALO 20480                 // [2][128][APAD] bf16 = 20480
#define SM_VHI 40960                 // [2][32][APAD]  bf16 =  5120
#define SM_VLO 46080                 // [2][32][APAD]  bf16 =  5120
#define SM_WS  51200                 // [32][36] float =  4608
#define MIXM_SMEM 55808

__global__ __launch_bounds__(256, 2)
void k_mixm(const float* __restrict__ z, const float* __restrict__ Amat,
            const float* __restrict__ hmat, float* __restrict__ out)
{
    extern __shared__ __align__(16) char smraw[];
    __nv_bfloat16* AsH = reinterpret_cast<__nv_bfloat16*>(smraw + SM_AHI);
    __nv_bfloat16* AsL = reinterpret_cast<__nv_bfloat16*>(smraw + SM_ALO);
    __nv_bfloat16* VsH = reinterpret_cast<__nv_bfloat16*>(smraw + SM_VHI);
    __nv_bfloat16* VsL = reinterpret_cast<__nv_bfloat16*>(smraw + SM_VLO);
    float* w_s = reinterpret_cast<float*>(smraw + SM_WS);   // [e][36]

    int tid = threadIdx.x;
    int warp = tid >> 5, lane = tid & 31;
    int g = lane >> 2, t = lane & 3;
    int b0 = blockIdx.x * NB;
    int m_off = warp * 16;

    // stage w_s[e][b]
    #pragma unroll
    for (int r = 0; r < 4; ++r) {
        int idx = tid + r * 256;
        int bb = idx >> 5, e = idx & 31;
        w_s[e * 36 + bb] = g_w[(size_t)(b0 + bb) * 32 + e];
    }
    __syncthreads();   // w_s visible before prologue reads it (R16 race fix)

    float D1[NTILES_N][4], D2[NTILES_N][4];
    #pragma unroll
    for (int nt = 0; nt < NTILES_N; ++nt)
        #pragma unroll
        for (int j = 0; j < 4; ++j) { D1[nt][j] = 0.f; D2[nt][j] = 0.f; }

    // thread roles for staging
    int am = tid >> 1, aq = tid & 1;           // A: 128 m rows x 2 float4-pairs
    int vk = tid >> 3, vb = (tid & 7) << 2;    // V: 32 k x 8 b-quads

    // ---- prologue: stage chunk 0 into stage 0 ----
    {
        const float4* ghi = reinterpret_cast<const float4*>(g_wx_hi);
        const float4* glo = reinterpret_cast<const float4*>(g_wx_lo);
        #pragma unroll
        for (int r = 0; r < 2; ++r) {
            int q = aq * 2 + r;                               // 0..3 (4 float4 per 32k row)
            float4 vh = ghi[am * 16 + q];
            float4 vl = glo[am * 16 + q];
            *reinterpret_cast<float4*>(&AsH[am * APAD + q * 8]) = vh;
            *reinterpret_cast<float4*>(&AsL[am * APAD + q * 8]) = vl;
        }
        float4 v = *reinterpret_cast<const float4*>(z + (size_t)vk * Bdim + b0 + vb);
        float w0 = w_s[0 * 36 + vb], w1 = w_s[0 * 36 + vb + 1];
        float w2 = w_s[0 * 36 + vb + 2], w3 = w_s[0 * 36 + vb + 3];
        float vv[4] = {v.x * w0, v.y * w1, v.z * w2, v.w * w3};
        #pragma unroll
        for (int i = 0; i < 4; ++i) {
            __nv_bfloat16 hh = __float2bfloat16(vv[i]);
            VsH[(vb + i) * APAD + vk] = hh;
            VsL[(vb + i) * APAD + vk] = __float2bfloat16(vv[i] - __bfloat162float(hh));
        }
    }
    __syncthreads();

    // ---- main pipeline: 128 chunks, ONE sync each ----
    float4 rAh[2], rAl[2], rV;
    for (int c = 0; c < 128; ++c) {
        int s = c & 1;
        int en = 0, k0n = 0;
        if (c < 127) {
            en = (c + 1) >> 2; k0n = ((c + 1) & 3) << 5;
            const float4* ghi = reinterpret_cast<const float4*>(g_wx_hi + (en << 14) + k0n);
            const float4* glo = reinterpret_cast<const float4*>(g_wx_lo + (en << 14) + k0n);
            #pragma unroll
            for (int r = 0; r < 2; ++r) {
                int q = aq * 2 + r;
                rAh[r] = ghi[am * 16 + q];
                rAl[r] = glo[am * 16 + q];
            }
            int kl = k0n + vk;
            rV = *reinterpret_cast<const float4*>(z + (size_t)kl * Bdim + b0 + vb);
        }

        // ---- MMA phase on stage s (hides the LDGs above) ----
        const __nv_bfloat16* ah_s = AsH + s * (128 * APAD);
        const __nv_bfloat16* al_s = AsL + s * (128 * APAD);
        const __nv_bfloat16* bh_s = VsH + s * (32 * APAD);
        const __nv_bfloat16* bl_s = VsL + s * (32 * APAD);
        #pragma unroll
        for (int sk = 0; sk < 2; ++sk) {
            int kb = sk << 4;
            uint32_t ah[4], al[4];
            ah[0] = *reinterpret_cast<const uint32_t*>(&ah_s[(m_off + g) * APAD + kb + 2 * t]);
            ah[1] = *reinterpret_cast<const uint32_t*>(&ah_s[(m_off + g + 8) * APAD + kb + 2 * t]);
            ah[2] = *reinterpret_cast<const uint32_t*>(&ah_s[(m_off + g) * APAD + kb + 2 * t + 8]);
            ah[3] = *reinterpret_cast<const uint32_t*>(&ah_s[(m_off + g + 8) * APAD + kb + 2 * t + 8]);
            al[0] = *reinterpret_cast<const uint32_t*>(&al_s[(m_off + g) * APAD + kb + 2 * t]);
            al[1] = *reinterpret_cast<const uint32_t*>(&al_s[(m_off + g + 8) * APAD + kb + 2 * t]);
            al[2] = *reinterpret_cast<const uint32_t*>(&al_s[(m_off + g) * APAD + kb + 2 * t + 8]);
            al[3] = *reinterpret_cast<const uint32_t*>(&al_s[(m_off + g + 8) * APAD + kb + 2 * t + 8]);
            #pragma unroll
            for (int nt = 0; nt < NTILES_N; ++nt) {
                uint32_t bh[2], bl[2];
                bh[0] = *reinterpret_cast<const uint32_t*>(&bh_s[((nt << 3) + g) * APAD + kb + 2 * t]);
                bh[1] = *reinterpret_cast<const uint32_t*>(&bh_s[((nt << 3) + g) * APAD + kb + 2 * t + 8]);
                bl[0] = *reinterpret_cast<const uint32_t*>(&bl_s[((nt << 3) + g) * APAD + kb + 2 * t]);
                bl[1] = *reinterpret_cast<const uint32_t*>(&bl_s[((nt << 3) + g) * APAD + kb + 2 * t + 8]);
                asm volatile(
                    "mma.sync.aligned.m16n8k16.row.col.f32.bf16.bf16.f32 "
                    "{%0,%1,%2,%3}, {%4,%5,%6,%7}, {%8,%9}, {%0,%1,%2,%3};"
                    : "+f"(D1[nt][0]), "+f"(D1[nt][1]), "+f"(D1[nt][2]), "+f"(D1[nt][3])
                    : "r"(ah[0]), "r"(ah[1]), "r"(ah[2]), "r"(ah[3]), "r"(bh[0]), "r"(bh[1]));
                asm volatile(
                    "mma.sync.aligned.m16n8k16.row.col.f32.bf16.bf16.f32 "
                    "{%0,%1,%2,%3}, {%4,%5,%6,%7}, {%8,%9}, {%0,%1,%2,%3};"
                    : "+f"(D1[nt][0]), "+f"(D1[nt][1]), "+f"(D1[nt][2]), "+f"(D1[nt][3])
                    : "r"(ah[0]), "r"(ah[1]), "r"(ah[2]), "r"(ah[3]), "r"(bl[0]), "r"(bl[1]));
                asm volatile(
                    "mma.sync.aligned.m16n8k16.row.col.f32.bf16.bf16.f32 "
                    "{%0,%1,%2,%3}, {%4,%5,%6,%7}, {%8,%9}, {%0,%1,%2,%3};"
                    : "+f"(D1[nt][0]), "+f"(D1[nt][1]), "+f"(D1[nt][2]), "+f"(D1[nt][3])
                    : "r"(al[0]), "r"(al[1]), "r"(al[2]), "r"(al[3]), "r"(bh[0]), "r"(bh[1]));
            }
        }

        // ---- write prefetched chunk c+1 into stage s^1 ----
        if (c < 127) {
            int sn = s ^ 1;
            __nv_bfloat16* ah_d = AsH + sn * (128 * APAD);
            __nv_bfloat16* al_d = AsL + sn * (128 * APAD);
            __nv_bfloat16* bh_d = VsH + sn * (32 * APAD);
            __nv_bfloat16* bl_d = VsL + sn * (32 * APAD);
            #pragma unroll
            for (int r = 0; r < 2; ++r) {
                int q = aq * 2 + r;
                *reinterpret_cast<float4*>(&ah_d[am * APAD + q * 8]) = rAh[r];
                *reinterpret_cast<float4*>(&al_d[am * APAD + q * 8]) = rAl[r];
            }
            int kl = k0n + vk;
            float4 v = rV;
            if (kl >= Mdim - 2) {
                v.x = fmaxf(v.x, 0.f); v.y = fmaxf(v.y, 0.f);
                v.z = fmaxf(v.z, 0.f); v.w = fmaxf(v.w, 0.f);
            }
            float vv[4] = {v.x * w_s[en * 36 + vb], v.y * w_s[en * 36 + vb + 1],
                           v.z * w_s[en * 36 + vb + 2], v.w * w_s[en * 36 + vb + 3]};
            #pragma unroll
            for (int i = 0; i < 4; ++i) {
                __nv_bfloat16 hh = __float2bfloat16(vv[i]);
                bh_d[(vb + i) * APAD + vk] = hh;
                bl_d[(vb + i) * APAD + vk] = __float2bfloat16(vv[i] - __bfloat162float(hh));
            }
        }
        __syncthreads();
    }

    // ---- tail chunks: h-term into D1, A-term into D2 ----
    #pragma unroll
    for (int tc = 0; tc < 2; ++tc) {
        const float* src = (tc == 0) ? hmat : Amat;
        #pragma unroll
        for (int r = 0; r < 16; ++r) {
            int idx = tid + (r << 8);
            int e2 = idx >> 7, m = idx & 127;
            float v = src[idx];
            __nv_bfloat16 hh = __float2bfloat16(v);
            AsH[m * APAD + e2] = hh;
            AsL[m * APAD + e2] = __float2bfloat16(v - __bfloat162float(hh));
        }
        if (tc == 0) {
            #pragma unroll
            for (int r = 0; r < 4; ++r) {
                int idx = tid + (r << 8);
                int bb = idx >> 5, e2 = idx & 31;
                float v = w_s[e2 * 36 + bb];
                __nv_bfloat16 hh = __float2bfloat16(v);
                VsH[bb * APAD + e2] = hh;
                VsL[bb * APAD + e2] = __float2bfloat16(v - __bfloat162float(hh));
            }
        }
        __syncthreads();

        float (*D)[4] = (tc == 0) ? D1 : D2;
        #pragma unroll
        for (int sk = 0; sk < 2; ++sk) {
            int kb = sk << 4;
            uint32_t ah[4], al[4];
            ah[0] = *reinterpret_cast<const uint32_t*>(&AsH[(m_off + g) * APAD + kb + 2 * t]);
            ah[1] = *reinterpret_cast<const uint32_t*>(&AsH[(m_off + g + 8) * APAD + kb + 2 * t]);
            ah[2] = *reinterpret_cast<const uint32_t*>(&AsH[(m_off + g) * APAD + kb + 2 * t + 8]);
            ah[3] = *reinterpret_cast<const uint32_t*>(&AsH[(m_off + g + 8) * APAD + kb + 2 * t + 8]);
            al[0] = *reinterpret_cast<const uint32_t*>(&AsL[(m_off + g) * APAD + kb + 2 * t]);
            al[1] = *reinterpret_cast<const uint32_t*>(&AsL[(m_off + g + 8) * APAD + kb + 2 * t]);
            al[2] = *reinterpret_cast<const uint32_t*>(&AsL[(m_off + g) * APAD + kb + 2 * t + 8]);
            al[3] = *reinterpret_cast<const uint32_t*>(&AsL[(m_off + g + 8) * APAD + kb + 2 * t + 8]);
            #pragma unroll
            for (int nt = 0; nt < NTILES_N; ++nt) {
                uint32_t bh[2], bl[2];
                bh[0] = *reinterpret_cast<const uint32_t*>(&VsH[((nt << 3) + g) * APAD + kb + 2 * t]);
                bh[1] = *reinterpret_cast<const uint32_t*>(&VsH[((nt << 3) + g) * APAD + kb + 2 * t + 8]);
                bl[0] = *reinterpret_cast<const uint32_t*>(&VsL[((nt << 3) + g) * APAD + kb + 2 * t]);
                bl[1] = *reinterpret_cast<const uint32_t*>(&VsL[((nt << 3) + g) * APAD + kb + 2 * t + 8]);
                asm volatile(
                    "mma.sync.aligned.m16n8k16.row.col.f32.bf16.bf16.f32 "
                    "{%0,%1,%2,%3}, {%4,%5,%6,%7}, {%8,%9}, {%0,%1,%2,%3};"
                    : "+f"(D[nt][0]), "+f"(D[nt][1]), "+f"(D[nt][2]), "+f"(D[nt][3])
                    : "r"(ah[0]), "r"(ah[1]), "r"(ah[2]), "r"(ah[3]), "r"(bh[0]), "r"(bh[1]));
                asm volatile(
                    "mma.sync.aligned.m16n8k16.row.col.f32.bf16.bf16.f32 "
                    "{%0,%1,%2,%3}, {%4,%5,%6,%7}, {%8,%9}, {%0,%1,%2,%3};"
                    : "+f"(D[nt][0]), "+f"(D[nt][1]), "+f"(D[nt][2]), "+f"(D[nt][3])
                    : "r"(ah[0]), "r"(ah[1]), "r"(ah[2]), "r"(ah[3]), "r"(bl[0]), "r"(bl[1]));
                asm volatile(
                    "mma.sync.aligned.m16n8k16.row.col.f32.bf16.bf16.f32 "
                    "{%0,%1,%2,%3}, {%4,%5,%6,%7}, {%8,%9}, {%0,%1,%2,%3};"
                    : "+f"(D[nt][0]), "+f"(D[nt][1]), "+f"(D[nt][2]), "+f"(D[nt][3])
                    : "r"(al[0]), "r"(al[1]), "r"(al[2]), "r"(al[3]), "r"(bh[0]), "r"(bh[1]));
            }
        }
        __syncthreads();
    }

    // ---- epilogue: out = D1 + z .* D2 ----
    #pragma unroll
    for (int nt = 0; nt < NTILES_N; ++nt) {
        int cb = b0 + (nt << 3) + 2 * t;
        int m0r = m_off + g, m1r = m_off + g + 8;
        float2 z0 = *reinterpret_cast<const float2*>(z + (size_t)m0r * Bdim + cb);
        float2 z1 = *reinterpret_cast<const float2*>(z + (size_t)m1r * Bdim + cb);
        float2 o0, o1;
        o0.x = D1[nt][0] + z0.x * D2[nt][0];
        o0.y = D1[nt][1] + z0.y * D2[nt][1];
        o1.x = D1[nt][2] + z1.x * D2[nt][2];
        o1.y = D1[nt][3] + z1.y * D2[nt][3];
        *reinterpret_cast<float2*>(out + (size_t)m0r * Bdim + cb) = o0;
        *reinterpret_cast<float2*>(out + (size_t)m1r * Bdim + cb) = o1;
    }
}

// ---------------- launch ----------------
extern "C" void kernel_launch(void* const* d_in, const int* in_sizes, int n_in,
                              void* d_out, int out_size)
{
    const float* z       = (const float*)d_in[0];
    const float* ctx     = (const float*)d_in[1];
    const float* noise   = (const float*)d_in[2];
    const float* conv_w  = (const float*)d_in[3];
    const float* conv_b  = (const float*)d_in[4];
    const float* Dm      = (const float*)d_in[5];
    const float* sigma_g = (const float*)d_in[6];
    const float* temp1   = (const float*)d_in[7];
    const float* W1      = (const float*)d_in[8];
    const float* b1      = (const float*)d_in[9];
    const float* W2      = (const float*)d_in[10];
    const float* b2      = (const float*)d_in[11];
    const float* temp2   = (const float*)d_in[12];
    const float* Amat    = (const float*)d_in[13];
    const float* Wx      = (const float*)d_in[14];
    const float* hmat    = (const float*)d_in[15];
    float* out = (float*)d_out;

    static int smem_set = 0;
    if (!smem_set) {
        cudaFuncSetAttribute(k_mixm, cudaFuncAttributeMaxDynamicSharedMemorySize, MIXM_SMEM);
        smem_set = 1;
    }

    k_conv<<<(Edim * Mdim * Mdim) / 256, 256>>>(Wx);
    k_zc<<<dim3(Bdim / 256, Ndim), 256>>>(z, noise, Dm, sigma_g);
    k_attn<<<Bdim / K2_WARPS, 256>>>(ctx, z, conv_w, conv_b, temp1, W1, b1, W2, b2, temp2);
    k_mixm<<<Bdim / NB, 256, MIXM_SMEM>>>(z, Amat, hmat, out);
}